// round 2
// baseline (speedup 1.0000x reference)
#include <cuda_runtime.h>

#define NN 50000
#define NE 800000
#define F  128
#define NG 100

// ---- scratch (static __device__ globals; no allocation anywhere) ----
__device__ __align__(16) float g_deg[NN];
__device__ __align__(16) float g_dinv[NN];
__device__ __align__(16) float g_norm[NE];
__device__ __align__(16) float g_h[NN * F];     // X @ W^T for current layer
__device__ __align__(16) float g_agg[NN * F];   // aggregation accumulator
__device__ __align__(16) float g_act[NN * F];   // post-ReLU activations
__device__ __align__(16) float g_pool[NG * F];
__device__ __align__(16) float g_cnt[NG];

// ---- zero deg / pool / cnt ----
__global__ void zero_misc_kernel() {
    int i = blockIdx.x * blockDim.x + threadIdx.x;
    if (i < NN) g_deg[i] = 0.f;
    if (i < NG * F) g_pool[i] = 0.f;
    if (i < NG) g_cnt[i] = 0.f;
}

// ---- deg[i] = sum of ew into col i (self-loop +1 folded into dinv) ----
__global__ void deg_kernel(const int* __restrict__ ei,
                           const float* __restrict__ ew) {
    int e = blockIdx.x * blockDim.x + threadIdx.x;
    if (e < NE) atomicAdd(&g_deg[ei[NE + e]], ew[e]);
}

__global__ void dinv_kernel() {
    int i = blockIdx.x * blockDim.x + threadIdx.x;
    if (i < NN) g_dinv[i] = rsqrtf(g_deg[i] + 1.0f);
}

__global__ void norm_kernel(const int* __restrict__ ei,
                            const float* __restrict__ ew) {
    int e = blockIdx.x * blockDim.x + threadIdx.x;
    if (e < NE) g_norm[e] = g_dinv[ei[e]] * ew[e] * g_dinv[ei[NE + e]];
}

// ---- C[n x 128] = X[n x 128] @ W^T, W row-major [128][128] ----
// block: 256 threads, 64 rows; thread (cx,ry) computes 8 rows x 4 cols.
__global__ void gemm128_kernel(const float* __restrict__ Xext,
                               const float* __restrict__ W,
                               int use_act, int n) {
    __shared__ __align__(16) float Ws[32][132];  // Ws[k_local][o]
    __shared__ float Xs[64][32];

    const float* __restrict__ X = use_act ? g_act : Xext;

    int tid = threadIdx.x;
    int cx = tid & 31;       // col group: outputs cx*4 .. cx*4+3
    int ry = tid >> 5;       // 0..7 (== warp id)
    int row0 = blockIdx.x * 64;

    float acc[8][4];
#pragma unroll
    for (int a = 0; a < 8; a++)
#pragma unroll
        for (int b = 0; b < 4; b++) acc[a][b] = 0.f;

    for (int kc = 0; kc < 4; kc++) {
        // load W chunk transposed: Ws[kl][o] = W[o][kc*32+kl]
#pragma unroll
        for (int oo = ry; oo < 128; oo += 8)
            Ws[cx][oo] = W[oo * 128 + kc * 32 + cx];
        // load X chunk
#pragma unroll
        for (int rr = ry; rr < 64; rr += 8) {
            int r = row0 + rr;
            Xs[rr][cx] = (r < n) ? X[(long long)r * 128 + kc * 32 + cx] : 0.f;
        }
        __syncthreads();

#pragma unroll
        for (int k = 0; k < 32; k++) {
            float4 w = *reinterpret_cast<const float4*>(&Ws[k][cx * 4]);
#pragma unroll
            for (int rr = 0; rr < 8; rr++) {
                float xv = Xs[ry + (rr << 3)][k];
                acc[rr][0] += xv * w.x;
                acc[rr][1] += xv * w.y;
                acc[rr][2] += xv * w.z;
                acc[rr][3] += xv * w.w;
            }
        }
        __syncthreads();
    }

#pragma unroll
    for (int rr = 0; rr < 8; rr++) {
        int r = row0 + ry + (rr << 3);
        if (r < n) {
            float4 o = make_float4(acc[rr][0], acc[rr][1], acc[rr][2], acc[rr][3]);
            *reinterpret_cast<float4*>(&g_h[(long long)r * 128 + cx * 4]) = o;
        }
    }
}

// ---- agg[i][f] = dinv[i]^2 * h[i][f] + b[f]  (self-loop + bias + zero-init) ----
__global__ void init_agg_kernel(const float* __restrict__ b) {
    int i = blockIdx.x * blockDim.x + threadIdx.x;  // float4 index
    if (i < NN * (F / 4)) {
        int node = i >> 5;
        float s = g_dinv[node];
        s = s * s;
        float4 hv = reinterpret_cast<const float4*>(g_h)[i];
        float4 bv = reinterpret_cast<const float4*>(b)[i & 31];
        float4 o = make_float4(hv.x * s + bv.x, hv.y * s + bv.y,
                               hv.z * s + bv.z, hv.w * s + bv.w);
        reinterpret_cast<float4*>(g_agg)[i] = o;
    }
}

// ---- edge scatter: agg[col] += norm * h[row]; one warp per edge ----
__global__ void scatter_kernel(const int* __restrict__ ei) {
    int w = (blockIdx.x * blockDim.x + threadIdx.x) >> 5;
    int lane = threadIdx.x & 31;
    if (w >= NE) return;
    float nrm = g_norm[w];
    int r = ei[w];
    int c = ei[NE + w];
    float4 v = reinterpret_cast<const float4*>(g_h)[(long long)r * 32 + lane];
    float* dst = g_agg + (long long)c * 128 + lane * 4;
    atomicAdd(dst + 0, v.x * nrm);
    atomicAdd(dst + 1, v.y * nrm);
    atomicAdd(dst + 2, v.z * nrm);
    atomicAdd(dst + 3, v.w * nrm);
}

// ---- act = relu(agg) ----
__global__ void relu_kernel() {
    int i = blockIdx.x * blockDim.x + threadIdx.x;
    if (i < NN * (F / 4)) {
        float4 v = reinterpret_cast<const float4*>(g_agg)[i];
        float4 o = make_float4(fmaxf(v.x, 0.f), fmaxf(v.y, 0.f),
                               fmaxf(v.z, 0.f), fmaxf(v.w, 0.f));
        reinterpret_cast<float4*>(g_act)[i] = o;
    }
}

// ---- mean-pool: warp per node ----
__global__ void pool_kernel(const int* __restrict__ batch) {
    int w = (blockIdx.x * blockDim.x + threadIdx.x) >> 5;
    int lane = threadIdx.x & 31;
    if (w >= NN) return;
    int g = batch[w];
    if (g < 0) g = 0;
    if (g >= NG) g = NG - 1;
    float4 v = reinterpret_cast<const float4*>(g_act)[(long long)w * 32 + lane];
    float* dst = &g_pool[g * F + lane * 4];
    atomicAdd(dst + 0, v.x);
    atomicAdd(dst + 1, v.y);
    atomicAdd(dst + 2, v.z);
    atomicAdd(dst + 3, v.w);
    if (lane == 0) atomicAdd(&g_cnt[g], 1.0f);
}

// ---- head MLP: one block per graph ----
__global__ void head_kernel(const float* __restrict__ l1w, const float* __restrict__ l1b,
                            const float* __restrict__ l2w, const float* __restrict__ l2b,
                            float* __restrict__ out) {
    int g = blockIdx.x;
    int t = threadIdx.x;
    __shared__ float gv[F];
    __shared__ float hv[F];
    __shared__ float red[F];

    float c = fmaxf(g_cnt[g], 1.0f);
    gv[t] = g_pool[g * F + t] / c;
    __syncthreads();

    float s = l1b[t];
    const float* wrow = l1w + t * F;
#pragma unroll 8
    for (int k = 0; k < F; k++) s += wrow[k] * gv[k];
    hv[t] = fmaxf(s, 0.f);
    __syncthreads();

    for (int o = 0; o < 2; o++) {
        red[t] = l2w[o * F + t] * hv[t];
        __syncthreads();
        for (int st = 64; st > 0; st >>= 1) {
            if (t < st) red[t] += red[t + st];
            __syncthreads();
        }
        if (t == 0) out[g * 2 + o] = red[0] + l2b[o];
        __syncthreads();
    }
}

extern "C" void kernel_launch(void* const* d_in, const int* in_sizes, int n_in,
                              void* d_out, int out_size) {
    const float* x        = (const float*)d_in[0];
    const int*   ei       = (const int*)d_in[1];
    const float* ew       = (const float*)d_in[2];
    const int*   batch    = (const int*)d_in[3];
    const float* W1       = (const float*)d_in[4];
    const float* b1       = (const float*)d_in[5];
    const float* W2       = (const float*)d_in[6];
    const float* b2       = (const float*)d_in[7];
    const float* l1w      = (const float*)d_in[8];
    const float* l1b      = (const float*)d_in[9];
    const float* l2w      = (const float*)d_in[10];
    const float* l2b      = (const float*)d_in[11];
    float* out            = (float*)d_out;

    const int T = 256;
    zero_misc_kernel<<<(NN + T - 1) / T, T>>>();
    deg_kernel<<<(NE + T - 1) / T, T>>>(ei, ew);
    dinv_kernel<<<(NN + T - 1) / T, T>>>();
    norm_kernel<<<(NE + T - 1) / T, T>>>(ei, ew);

    int gemm_blocks = (NN + 63) / 64;
    int ew4_blocks  = (NN * (F / 4) + T - 1) / T;   // elementwise float4 grids
    int sc_blocks   = (NE * 32 + T - 1) / T;        // warp per edge
    int pool_blocks = (NN * 32 + T - 1) / T;        // warp per node

    // layer 1
    gemm128_kernel<<<gemm_blocks, T>>>(x, W1, 0, NN);
    init_agg_kernel<<<ew4_blocks, T>>>(b1);
    scatter_kernel<<<sc_blocks, T>>>(ei);
    relu_kernel<<<ew4_blocks, T>>>();

    // layer 2
    gemm128_kernel<<<gemm_blocks, T>>>(x, W2, 1, NN);
    init_agg_kernel<<<ew4_blocks, T>>>(b2);
    scatter_kernel<<<sc_blocks, T>>>(ei);
    relu_kernel<<<ew4_blocks, T>>>();

    // pool + head
    pool_kernel<<<pool_blocks, T>>>(batch);
    head_kernel<<<NG, F>>>(l1w, l1b, l2w, l2b, out);
}

// round 3
// speedup vs baseline: 2.1652x; 2.1652x over previous
#include <cuda_runtime.h>

#define NN 50000
#define NE 800000
#define F  128
#define NG 100
#define SCAN_B 1024
#define NSB ((NN + SCAN_B - 1) / SCAN_B)   // 49

// ---- scratch (static __device__ globals; no allocation anywhere) ----
__device__ __align__(16) float g_deg[NN];
__device__ __align__(16) float g_dinv[NN];
__device__ __align__(16) float g_h[NN * F];     // X @ W^T for current layer
__device__ __align__(16) float g_act[NN * F];   // post-ReLU activations
__device__ __align__(16) float g_pool[NG * F];
__device__ __align__(16) float g_cnt[NG];
// CSR-by-destination
__device__ int   g_cnt_in[NN];
__device__ int   g_incl[NN];
__device__ int   g_bsum[NSB];
__device__ int   g_boff[NSB];
__device__ int   g_ptr[NN + 1];
__device__ int   g_cur[NN];
__device__ __align__(16) int   g_csr_row[NE];
__device__ __align__(16) float g_csr_norm[NE];

// ---- zero deg / histogram / pool / cnt ----
__global__ void zero_misc_kernel() {
    int i = blockIdx.x * blockDim.x + threadIdx.x;
    if (i < NN) { g_deg[i] = 0.f; g_cnt_in[i] = 0; }
    if (i < NG * F) g_pool[i] = 0.f;
    if (i < NG) g_cnt[i] = 0.f;
}

// ---- deg[c] += ew; hist[c] += 1 ----
__global__ void deg_count_kernel(const int* __restrict__ ei,
                                 const float* __restrict__ ew) {
    int e = blockIdx.x * blockDim.x + threadIdx.x;
    if (e < NE) {
        int c = ei[NE + e];
        atomicAdd(&g_deg[c], ew[e]);
        atomicAdd(&g_cnt_in[c], 1);
    }
}

// ---- dinv + per-graph node counts ----
__global__ void dinv_kernel(const int* __restrict__ batch) {
    int i = blockIdx.x * blockDim.x + threadIdx.x;
    if (i < NN) {
        g_dinv[i] = rsqrtf(g_deg[i] + 1.0f);   // +1 = self-loop weight
        int g = batch[i];
        if (g < 0) g = 0;
        if (g >= NG) g = NG - 1;
        atomicAdd(&g_cnt[g], 1.0f);
    }
}

// ---- inclusive scan of hist, per 1024-block ----
__global__ void scan1_kernel() {
    __shared__ int s[SCAN_B];
    int tid = threadIdx.x;
    int i = blockIdx.x * SCAN_B + tid;
    int v = (i < NN) ? g_cnt_in[i] : 0;
    s[tid] = v;
    __syncthreads();
#pragma unroll
    for (int off = 1; off < SCAN_B; off <<= 1) {
        int t = (tid >= off) ? s[tid - off] : 0;
        __syncthreads();
        s[tid] += t;
        __syncthreads();
    }
    if (i < NN) g_incl[i] = s[tid];
    if (tid == SCAN_B - 1) g_bsum[blockIdx.x] = s[tid];
}

__global__ void scan2_kernel() {
    if (threadIdx.x == 0) {
        int run = 0;
        for (int b = 0; b < NSB; b++) { g_boff[b] = run; run += g_bsum[b]; }
    }
}

__global__ void scan3_kernel() {
    int i = blockIdx.x * blockDim.x + threadIdx.x;
    if (i < NN) {
        int t = g_incl[i] + g_boff[i >> 10];  // inclusive prefix through i
        g_ptr[i + 1] = t;
        g_cur[i] = t - g_cnt_in[i];           // exclusive start
        if (i == 0) g_ptr[0] = 0;
    }
}

// ---- scatter edges into CSR slots; fold norm computation in ----
__global__ void fill_kernel(const int* __restrict__ ei,
                            const float* __restrict__ ew) {
    int e = blockIdx.x * blockDim.x + threadIdx.x;
    if (e < NE) {
        int r = ei[e];
        int c = ei[NE + e];
        int pos = atomicAdd(&g_cur[c], 1);
        g_csr_row[pos] = r;
        g_csr_norm[pos] = g_dinv[r] * ew[e] * g_dinv[c];
    }
}

// ---- C[n x 128] = X @ W^T ; 128x128 tile, 8x8 per-thread register blocking ----
__global__ void __launch_bounds__(256, 2)
gemm128_kernel(const float* __restrict__ Xext, const float* __restrict__ W,
               int use_act, int n) {
    __shared__ __align__(16) float Xs[16][136];  // [k][row]
    __shared__ __align__(16) float Ws[16][136];  // [k][out]

    const float* __restrict__ X = use_act ? g_act : Xext;

    int tid = threadIdx.x;
    int cx = tid & 15;        // col group: cols cx*8 .. cx*8+7
    int ry = tid >> 4;        // row group: rows ry*8 .. ry*8+7
    int row0 = blockIdx.x * 128;

    int lr   = tid >> 1;      // 0..127 : load row / out index
    int half = tid & 1;       // which 8-wide k half

    float acc[8][8];
#pragma unroll
    for (int a = 0; a < 8; a++)
#pragma unroll
        for (int b = 0; b < 8; b++) acc[a][b] = 0.f;

    for (int kc = 0; kc < 8; kc++) {
        int kbase = kc * 16 + half * 8;
        // X chunk (transposed into smem)
        {
            int r = row0 + lr;
            float4 a0, a1;
            if (r < n) {
                a0 = *reinterpret_cast<const float4*>(&X[(long long)r * 128 + kbase]);
                a1 = *reinterpret_cast<const float4*>(&X[(long long)r * 128 + kbase + 4]);
            } else {
                a0 = make_float4(0.f, 0.f, 0.f, 0.f);
                a1 = a0;
            }
            int kb = half * 8;
            Xs[kb + 0][lr] = a0.x; Xs[kb + 1][lr] = a0.y;
            Xs[kb + 2][lr] = a0.z; Xs[kb + 3][lr] = a0.w;
            Xs[kb + 4][lr] = a1.x; Xs[kb + 5][lr] = a1.y;
            Xs[kb + 6][lr] = a1.z; Xs[kb + 7][lr] = a1.w;
        }
        // W chunk (transposed into smem): Ws[k][o] = W[o][kc*16+k]
        {
            float4 w0 = *reinterpret_cast<const float4*>(&W[lr * 128 + kbase]);
            float4 w1 = *reinterpret_cast<const float4*>(&W[lr * 128 + kbase + 4]);
            int kb = half * 8;
            Ws[kb + 0][lr] = w0.x; Ws[kb + 1][lr] = w0.y;
            Ws[kb + 2][lr] = w0.z; Ws[kb + 3][lr] = w0.w;
            Ws[kb + 4][lr] = w1.x; Ws[kb + 5][lr] = w1.y;
            Ws[kb + 6][lr] = w1.z; Ws[kb + 7][lr] = w1.w;
        }
        __syncthreads();

#pragma unroll
        for (int k = 0; k < 16; k++) {
            float4 x0 = *reinterpret_cast<const float4*>(&Xs[k][ry * 8]);
            float4 x1 = *reinterpret_cast<const float4*>(&Xs[k][ry * 8 + 4]);
            float4 w0 = *reinterpret_cast<const float4*>(&Ws[k][cx * 8]);
            float4 w1 = *reinterpret_cast<const float4*>(&Ws[k][cx * 8 + 4]);
            float xr[8] = {x0.x, x0.y, x0.z, x0.w, x1.x, x1.y, x1.z, x1.w};
            float wr[8] = {w0.x, w0.y, w0.z, w0.w, w1.x, w1.y, w1.z, w1.w};
#pragma unroll
            for (int a = 0; a < 8; a++)
#pragma unroll
                for (int b = 0; b < 8; b++) acc[a][b] += xr[a] * wr[b];
        }
        __syncthreads();
    }

#pragma unroll
    for (int a = 0; a < 8; a++) {
        int r = row0 + ry * 8 + a;
        if (r < n) {
            float4 o0 = make_float4(acc[a][0], acc[a][1], acc[a][2], acc[a][3]);
            float4 o1 = make_float4(acc[a][4], acc[a][5], acc[a][6], acc[a][7]);
            *reinterpret_cast<float4*>(&g_h[(long long)r * 128 + cx * 8])     = o0;
            *reinterpret_cast<float4*>(&g_h[(long long)r * 128 + cx * 8 + 4]) = o1;
        }
    }
}

// ---- fused aggregate: acc = dinv^2*h[i] + b + sum_e norm*h[row]; relu; (pool) ----
__global__ void gather_kernel(const float* __restrict__ bias,
                              const int* __restrict__ batch, int do_pool) {
    int w = (blockIdx.x * blockDim.x + threadIdx.x) >> 5;   // node
    int lane = threadIdx.x & 31;
    if (w >= NN) return;

    const float4* __restrict__ h4 = reinterpret_cast<const float4*>(g_h);
    int start = g_ptr[w];
    int end   = g_ptr[w + 1];
    float di = g_dinv[w];
    float s = di * di;

    float4 acc = h4[(long long)w * 32 + lane];
    float4 bv = reinterpret_cast<const float4*>(bias)[lane];
    acc.x = acc.x * s + bv.x;
    acc.y = acc.y * s + bv.y;
    acc.z = acc.z * s + bv.z;
    acc.w = acc.w * s + bv.w;

    int e = start;
    for (; e + 2 <= end; e += 2) {
        int   r0 = g_csr_row[e],     r1 = g_csr_row[e + 1];
        float n0 = g_csr_norm[e],    n1 = g_csr_norm[e + 1];
        float4 v0 = h4[(long long)r0 * 32 + lane];
        float4 v1 = h4[(long long)r1 * 32 + lane];
        acc.x += n0 * v0.x + n1 * v1.x;
        acc.y += n0 * v0.y + n1 * v1.y;
        acc.z += n0 * v0.z + n1 * v1.z;
        acc.w += n0 * v0.w + n1 * v1.w;
    }
    if (e < end) {
        int   r0 = g_csr_row[e];
        float n0 = g_csr_norm[e];
        float4 v0 = h4[(long long)r0 * 32 + lane];
        acc.x += n0 * v0.x; acc.y += n0 * v0.y;
        acc.z += n0 * v0.z; acc.w += n0 * v0.w;
    }

    acc.x = fmaxf(acc.x, 0.f); acc.y = fmaxf(acc.y, 0.f);
    acc.z = fmaxf(acc.z, 0.f); acc.w = fmaxf(acc.w, 0.f);
    reinterpret_cast<float4*>(g_act)[(long long)w * 32 + lane] = acc;

    if (do_pool) {
        int g = batch[w];
        if (g < 0) g = 0;
        if (g >= NG) g = NG - 1;
        float* dst = &g_pool[g * F + lane * 4];
        atomicAdd(dst + 0, acc.x);
        atomicAdd(dst + 1, acc.y);
        atomicAdd(dst + 2, acc.z);
        atomicAdd(dst + 3, acc.w);
    }
}

// ---- head MLP: one block per graph ----
__global__ void head_kernel(const float* __restrict__ l1w, const float* __restrict__ l1b,
                            const float* __restrict__ l2w, const float* __restrict__ l2b,
                            float* __restrict__ out) {
    int g = blockIdx.x;
    int t = threadIdx.x;
    __shared__ float gv[F];
    __shared__ float hv[F];
    __shared__ float red[F];

    float c = fmaxf(g_cnt[g], 1.0f);
    gv[t] = g_pool[g * F + t] / c;
    __syncthreads();

    float s = l1b[t];
    const float* wrow = l1w + t * F;
#pragma unroll 8
    for (int k = 0; k < F; k++) s += wrow[k] * gv[k];
    hv[t] = fmaxf(s, 0.f);
    __syncthreads();

    for (int o = 0; o < 2; o++) {
        red[t] = l2w[o * F + t] * hv[t];
        __syncthreads();
        for (int st = 64; st > 0; st >>= 1) {
            if (t < st) red[t] += red[t + st];
            __syncthreads();
        }
        if (t == 0) out[g * 2 + o] = red[0] + l2b[o];
        __syncthreads();
    }
}

extern "C" void kernel_launch(void* const* d_in, const int* in_sizes, int n_in,
                              void* d_out, int out_size) {
    const float* x     = (const float*)d_in[0];
    const int*   ei    = (const int*)d_in[1];
    const float* ew    = (const float*)d_in[2];
    const int*   batch = (const int*)d_in[3];
    const float* W1    = (const float*)d_in[4];
    const float* b1    = (const float*)d_in[5];
    const float* W2    = (const float*)d_in[6];
    const float* b2    = (const float*)d_in[7];
    const float* l1w   = (const float*)d_in[8];
    const float* l1b   = (const float*)d_in[9];
    const float* l2w   = (const float*)d_in[10];
    const float* l2b   = (const float*)d_in[11];
    float* out         = (float*)d_out;

    const int T = 256;
    // CSR build + norm
    zero_misc_kernel<<<(NN + T - 1) / T, T>>>();
    deg_count_kernel<<<(NE + T - 1) / T, T>>>(ei, ew);
    dinv_kernel<<<(NN + T - 1) / T, T>>>(batch);
    scan1_kernel<<<NSB, SCAN_B>>>();
    scan2_kernel<<<1, 32>>>();
    scan3_kernel<<<(NN + T - 1) / T, T>>>();
    fill_kernel<<<(NE + T - 1) / T, T>>>(ei, ew);

    int gemm_blocks   = (NN + 127) / 128;
    int gather_blocks = (NN * 32 + T - 1) / T;

    // layer 1
    gemm128_kernel<<<gemm_blocks, T>>>(x, W1, 0, NN);
    gather_kernel<<<gather_blocks, T>>>(b1, batch, 0);

    // layer 2 (+ fused mean-pool accumulation)
    gemm128_kernel<<<gemm_blocks, T>>>(x, W2, 1, NN);
    gather_kernel<<<gather_blocks, T>>>(b2, batch, 1);

    // head
    head_kernel<<<NG, F>>>(l1w, l1b, l2w, l2b, out);
}